// round 1
// baseline (speedup 1.0000x reference)
#include <cuda_runtime.h>

#define Hh 160
#define Ww 160
#define Bn 4
#define HW (Hh*Ww)

// ---------------- scratch (device globals; no allocation allowed) ----------------
__device__ float g_h1[(size_t)Bn*128*HW];     // conv1 out
__device__ float g_h2[(size_t)Bn*128*HW];     // conv2 out
__device__ float g_off[(size_t)Bn*18*HW];     // offset conv out
__device__ float g_hrT[(size_t)Bn*HW*64];     // hr in NHWC
__device__ float g_samp[(size_t)Bn*576*HW];   // bilinear samples, [b][c*9+k][h][w]
__device__ float g_w1T[1152*128];
__device__ float g_w2T[1152*128];
__device__ float g_woT[1152*32];              // padded 18 -> 32
__device__ float g_wdT[576*64];

// ---------------- weight reformat: [O][CINK] -> [CINK][O_pad] (zero padded) ----------------
__global__ void transpose_w(const float* __restrict__ w, float* __restrict__ wT,
                            int COUT, int COUT_PAD, int CINK)
{
    int i = blockIdx.x*blockDim.x + threadIdx.x;
    if (i >= CINK*COUT_PAD) return;
    int o = i % COUT_PAD;
    int j = i / COUT_PAD;
    wT[i] = (o < COUT) ? w[(size_t)o*CINK + j] : 0.f;
}

// ---------------- hr NCHW -> NHWC ----------------
__global__ void hr_transpose(const float* __restrict__ hr, float* __restrict__ hrT)
{
    int idx = blockIdx.x*blockDim.x + threadIdx.x;
    if (idx >= Bn*64*HW) return;
    int x = idx % Ww;
    int y = (idx / Ww) % Hh;
    int c = (idx / HW) % 64;
    int b = idx / (64*HW);
    hrT[(((size_t)b*HW) + (size_t)y*Ww + x)*64 + c] = hr[idx];
}

// ---------------- tiled direct conv / 1x1 GEMM ----------------
// Block tile: OC_TILE = OCG*4 output channels  x  128 pixels (32 wide x 4 rows).
// Thread: 4 contiguous oc x (4 contiguous x) x (2 rows) = 32 accumulators.
// Threads = OCG*16:  tx = t&7 (x group), tyy = (t>>3)&1 (row pair), tg = t>>4 (oc group).
// Weights pre-transposed: wT[(cin*KS*KS + k)*COUT_PAD + oc]  (coalesced staging).
template<int OCG, int KS, bool RELU>
__global__ void __launch_bounds__(OCG*16)
conv_tiled(const float* __restrict__ in0,
           const float* __restrict__ in1,     // second half of channel concat (or null)
           const float* __restrict__ wT,
           const float* __restrict__ bias,    // or null
           float* __restrict__ out,
           int CIN, int CIN0, int COUT, int COUT_PAD)
{
    constexpr int OC_TILE = OCG*4;
    constexpr int CK = 4;
    constexpr int KK = KS*KS;
    constexpr int SR = (KS==3) ? 6 : 4;
    constexpr int IW = (KS==3) ? 34 : 32;
    constexpr int SW = 36;
    constexpr int NT = OCG*16;

    __shared__ float s_in[CK][SR][SW];
    __shared__ float s_w[CK][KK][OC_TILE];

    const int t   = threadIdx.x;
    const int tx  = t & 7;
    const int tyy = (t >> 3) & 1;
    const int tg  = t >> 4;

    const int noct = COUT_PAD / OC_TILE;
    const int oct  = blockIdx.z % noct;
    const int b    = blockIdx.z / noct;
    const int xb   = blockIdx.x * 32;
    const int yb   = blockIdx.y * 4;
    const int oc0  = oct * OC_TILE;
    const int x0   = tx * 4;
    const int myoc = oc0 + tg*4;

    float bini[4];
    #pragma unroll
    for (int o = 0; o < 4; o++)
        bini[o] = (bias != nullptr && (myoc+o) < COUT) ? bias[myoc+o] : 0.f;

    float acc[2][4][4];
    #pragma unroll
    for (int r = 0; r < 2; r++)
        #pragma unroll
        for (int j = 0; j < 4; j++)
            #pragma unroll
            for (int o = 0; o < 4; o++)
                acc[r][j][o] = bini[o];

    const int CIN1 = CIN - CIN0;

    for (int ci0 = 0; ci0 < CIN; ci0 += CK) {
        // stage input tile (zero-padded halo for KS==3)
        for (int e = t; e < CK*SR*IW; e += NT) {
            int ci  = e / (SR*IW);
            int rem = e - ci*(SR*IW);
            int r   = rem / IW;
            int c   = rem - r*IW;
            int gy  = yb + r - (KS==3 ? 1 : 0);
            int gx  = xb + c - (KS==3 ? 1 : 0);
            float v = 0.f;
            if (gy >= 0 && gy < Hh && gx >= 0 && gx < Ww) {
                int cin = ci0 + ci;
                const float* p = (cin < CIN0)
                    ? (in0 + ((size_t)b*CIN0 + cin)*HW)
                    : (in1 + ((size_t)b*CIN1 + (cin - CIN0))*HW);
                v = p[gy*Ww + gx];
            }
            s_in[ci][r][c] = v;
        }
        // stage weights (coalesced: oc contiguous)
        for (int e = t; e < CK*KK*OC_TILE; e += NT) {
            int oc  = e % OC_TILE;
            int rem = e / OC_TILE;
            int k   = rem % KK;
            int ci  = rem / KK;
            s_w[ci][k][oc] = wT[((size_t)(ci0+ci)*KK + k)*COUT_PAD + oc0 + oc];
        }
        __syncthreads();

        #pragma unroll
        for (int ci = 0; ci < CK; ci++) {
            if (KS == 3) {
                #pragma unroll
                for (int ky = 0; ky < 3; ky++) {
                    const float* r0 = &s_in[ci][tyy*2 + ky][0];
                    const float* r1 = &s_in[ci][tyy*2 + 1 + ky][0];
                    float i0[6], i1[6];
                    float4 a0 = *(const float4*)(r0 + x0);
                    float4 a1 = *(const float4*)(r1 + x0);
                    i0[0]=a0.x; i0[1]=a0.y; i0[2]=a0.z; i0[3]=a0.w;
                    i0[4]=r0[x0+4]; i0[5]=r0[x0+5];
                    i1[0]=a1.x; i1[1]=a1.y; i1[2]=a1.z; i1[3]=a1.w;
                    i1[4]=r1[x0+4]; i1[5]=r1[x0+5];
                    #pragma unroll
                    for (int kx = 0; kx < 3; kx++) {
                        float4 wv = *(const float4*)&s_w[ci][ky*3+kx][tg*4];
                        float wa[4] = {wv.x, wv.y, wv.z, wv.w};
                        #pragma unroll
                        for (int j = 0; j < 4; j++) {
                            #pragma unroll
                            for (int o = 0; o < 4; o++) {
                                acc[0][j][o] += i0[j+kx]*wa[o];
                                acc[1][j][o] += i1[j+kx]*wa[o];
                            }
                        }
                    }
                }
            } else {
                float4 a0 = *(const float4*)&s_in[ci][tyy*2+0][x0];
                float4 a1 = *(const float4*)&s_in[ci][tyy*2+1][x0];
                float i0[4] = {a0.x, a0.y, a0.z, a0.w};
                float i1[4] = {a1.x, a1.y, a1.z, a1.w};
                float4 wv = *(const float4*)&s_w[ci][0][tg*4];
                float wa[4] = {wv.x, wv.y, wv.z, wv.w};
                #pragma unroll
                for (int j = 0; j < 4; j++) {
                    #pragma unroll
                    for (int o = 0; o < 4; o++) {
                        acc[0][j][o] += i0[j]*wa[o];
                        acc[1][j][o] += i1[j]*wa[o];
                    }
                }
            }
        }
        __syncthreads();
    }

    #pragma unroll
    for (int o = 0; o < 4; o++) {
        int oc = myoc + o;
        if (oc < COUT) {
            #pragma unroll
            for (int r = 0; r < 2; r++) {
                int y = yb + tyy*2 + r;
                float4 v;
                v.x = acc[r][0][o]; v.y = acc[r][1][o];
                v.z = acc[r][2][o]; v.w = acc[r][3][o];
                if (RELU) {
                    v.x = fmaxf(v.x, 0.f); v.y = fmaxf(v.y, 0.f);
                    v.z = fmaxf(v.z, 0.f); v.w = fmaxf(v.w, 0.f);
                }
                *(float4*)&out[((size_t)b*COUT + oc)*HW + (size_t)y*Ww + xb + x0] = v;
            }
        }
    }
}

// ---------------- bilinear sampling (hr in NHWC; 16 channels/thread via LDG.128) ----------------
// idx -> (b, k, cg, y, x); writes samp[b][(cg*16+c)*9 + k][y][x]
__global__ void deform_sample(const float* __restrict__ hrT,
                              const float* __restrict__ off,
                              float* __restrict__ samp)
{
    int idx = blockIdx.x*blockDim.x + threadIdx.x;
    if (idx >= Bn*9*4*HW) return;
    int x  = idx % Ww;
    int y  = (idx / Ww) % Hh;
    int cg = (idx / HW) & 3;
    int k  = (idx / (HW*4)) % 9;
    int b  = idx / (HW*36);
    int ky = k/3 - 1;
    int kx = k%3 - 1;

    size_t opix = ((size_t)b*18)*HW + (size_t)y*Ww + x;
    float dy = off[opix + (size_t)(2*k  )*HW];
    float dx = off[opix + (size_t)(2*k+1)*HW];

    float py = (float)(y + ky) + dy;
    float px = (float)(x + kx) + dx;
    float y0f = floorf(py), x0f = floorf(px);
    float wy = py - y0f, wx = px - x0f;
    int yi = (int)y0f, xi = (int)x0f;

    bool vy0 = (yi   >= 0) && (yi   <= Hh-1);
    bool vy1 = (yi+1 >= 0) && (yi+1 <= Hh-1);
    bool vx0 = (xi   >= 0) && (xi   <= Ww-1);
    bool vx1 = (xi+1 >= 0) && (xi+1 <= Ww-1);
    int yc0 = min(max(yi,   0), Hh-1);
    int yc1 = min(max(yi+1, 0), Hh-1);
    int xc0 = min(max(xi,   0), Ww-1);
    int xc1 = min(max(xi+1, 0), Ww-1);

    float w00 = (1.f-wy)*(1.f-wx) * ((vy0 && vx0) ? 1.f : 0.f);
    float w01 = (1.f-wy)*wx       * ((vy0 && vx1) ? 1.f : 0.f);
    float w10 = wy*(1.f-wx)       * ((vy1 && vx0) ? 1.f : 0.f);
    float w11 = wy*wx             * ((vy1 && vx1) ? 1.f : 0.f);

    const float* base = hrT + (size_t)b*HW*64 + cg*16;
    const float4* p00 = (const float4*)(base + ((size_t)yc0*Ww + xc0)*64);
    const float4* p01 = (const float4*)(base + ((size_t)yc0*Ww + xc1)*64);
    const float4* p10 = (const float4*)(base + ((size_t)yc1*Ww + xc0)*64);
    const float4* p11 = (const float4*)(base + ((size_t)yc1*Ww + xc1)*64);

    float o16[16];
    #pragma unroll
    for (int q = 0; q < 4; q++) {
        float4 a = p00[q], bq = p01[q], c4 = p10[q], d = p11[q];
        o16[q*4+0] = w00*a.x + w01*bq.x + w10*c4.x + w11*d.x;
        o16[q*4+1] = w00*a.y + w01*bq.y + w10*c4.y + w11*d.y;
        o16[q*4+2] = w00*a.z + w01*bq.z + w10*c4.z + w11*d.z;
        o16[q*4+3] = w00*a.w + w01*bq.w + w10*c4.w + w11*d.w;
    }

    size_t sb = ((size_t)b*576 + k)*HW + (size_t)y*Ww + x;
    #pragma unroll
    for (int c = 0; c < 16; c++)
        samp[sb + (size_t)(cg*16 + c)*9*HW] = o16[c];
}

// ---------------- launch ----------------
extern "C" void kernel_launch(void* const* d_in, const int* in_sizes, int n_in,
                              void* d_out, int out_size)
{
    (void)in_sizes; (void)n_in; (void)out_size;
    const float* lr = (const float*)d_in[0];
    const float* hr = (const float*)d_in[1];
    const float* w1 = (const float*)d_in[2];
    const float* b1 = (const float*)d_in[3];
    const float* w2 = (const float*)d_in[4];
    const float* b2 = (const float*)d_in[5];
    const float* wo = (const float*)d_in[6];
    const float* wd = (const float*)d_in[7];
    float* out = (float*)d_out;

    float *ph1, *ph2, *poff, *phrT, *psamp, *pw1T, *pw2T, *pwoT, *pwdT;
    cudaGetSymbolAddress((void**)&ph1,  g_h1);
    cudaGetSymbolAddress((void**)&ph2,  g_h2);
    cudaGetSymbolAddress((void**)&poff, g_off);
    cudaGetSymbolAddress((void**)&phrT, g_hrT);
    cudaGetSymbolAddress((void**)&psamp,g_samp);
    cudaGetSymbolAddress((void**)&pw1T, g_w1T);
    cudaGetSymbolAddress((void**)&pw2T, g_w2T);
    cudaGetSymbolAddress((void**)&pwoT, g_woT);
    cudaGetSymbolAddress((void**)&pwdT, g_wdT);

    // weight reformats + hr NHWC (cheap)
    transpose_w<<<(1152*128 + 255)/256, 256>>>(w1, pw1T, 128, 128, 1152);
    transpose_w<<<(1152*128 + 255)/256, 256>>>(w2, pw2T, 128, 128, 1152);
    transpose_w<<<(1152*32  + 255)/256, 256>>>(wo, pwoT, 18,  32,  1152);
    transpose_w<<<(576*64   + 255)/256, 256>>>(wd, pwdT, 64,  64,  576);
    hr_transpose<<<(Bn*64*HW + 255)/256, 256>>>(hr, phrT);

    // conv1: concat(lr,hr) -> 128, relu
    conv_tiled<16,3,true ><<<dim3(5,40,8), 256>>>(lr,  hr,      pw1T, b1,      ph1, 128, 64,  128, 128);
    // conv2: 128 -> 128, relu
    conv_tiled<16,3,true ><<<dim3(5,40,8), 256>>>(ph1, nullptr, pw2T, b2,      ph2, 128, 128, 128, 128);
    // offset conv: 128 -> 18 (padded 32)
    conv_tiled<8, 3,false><<<dim3(5,40,4), 128>>>(ph2, nullptr, pwoT, nullptr, poff,128, 128, 18,  32);
    // bilinear sampling
    deform_sample<<<(Bn*9*4*HW + 255)/256, 256>>>(phrT, poff, psamp);
    // deform contraction as 1x1 conv: 576 -> 64
    conv_tiled<16,1,false><<<dim3(5,40,4), 256>>>(psamp, nullptr, pwdT, nullptr, out, 576, 576, 64, 64);
}